// round 2
// baseline (speedup 1.0000x reference)
#include <cuda_runtime.h>
#include <cuda_bf16.h>

// PatchMerging: gather(2x2x2 stride-2 patches, concat 8*96=768) -> LayerNorm(768) -> Linear(768->192)
// Fused as a GEMM over raw gathered x with LN folded into the epilogue:
//   out[m,o] = rstd_m * dot(y_m, WgT[:,o]) + (bias_o - rstd_m*mu_m*s_o)
// where WgT[c][o] = ln_w[c]*W[o][c],  s_o = sum_c WgT[c][o],  bias_o = sum_c ln_b[c]*W[o][c].

#define M_TOTAL 65536   // 2*32*32*32
#define KDIM    768
#define NDIM    192
#define CH      96

#define TB  256
#define BM  64
#define BMP 68          // padded row pitch for transposed y tile (16B-aligned, bank-shifted)
#define KC  96          // K chunk = one patch segment

// Device scratch (no allocations allowed)
__device__ float g_WgT[KDIM * NDIM];   // [c][o], c-major for coalesced chunk loads
__device__ float g_s[NDIM];
__device__ float g_bias[NDIM];

__global__ void pm_prep_wgt(const float* __restrict__ ln_w, const float* __restrict__ W) {
    int idx = blockIdx.x * blockDim.x + threadIdx.x;
    if (idx < KDIM * NDIM) {
        int c = idx / NDIM;
        int o = idx - c * NDIM;
        g_WgT[idx] = ln_w[c] * W[o * KDIM + c];
    }
}

__global__ void pm_prep_cols(const float* __restrict__ ln_w, const float* __restrict__ ln_b,
                             const float* __restrict__ W) {
    int o = threadIdx.x;
    if (o < NDIM) {
        float s = 0.f, b = 0.f;
        const float* wr = W + o * KDIM;
        for (int c = 0; c < KDIM; ++c) {
            float w = wr[c];
            s = fmaf(ln_w[c], w, s);
            b = fmaf(ln_b[c], w, b);
        }
        g_s[o] = s;
        g_bias[o] = b;
    }
}

// Dyn smem layout: ys[KC*BMP] | ws[KC*NDIM] | rsum[BM] | rsq[BM]
#define SMEM_FLOATS (KC * BMP + KC * NDIM + 2 * BM)

__global__ __launch_bounds__(TB, 2) void pm_main(const float* __restrict__ x,
                                                 float* __restrict__ out) {
    extern __shared__ float smem[];
    float* ys   = smem;                  // transposed y tile: ys[k*BMP + row]
    float* ws   = smem + KC * BMP;       // W chunk:          ws[k*NDIM + o]
    float* rsum = ws + KC * NDIM;
    float* rsq  = rsum + BM;

    const int tid = threadIdx.x;
    const int tx = tid & 15;             // 0..15 -> N
    const int ty = tid >> 4;             // 0..15 -> M
    const int r0 = ty * 4;
    const int c0 = tx * 12;
    const int bm = blockIdx.x;

    if (tid < BM) { rsum[tid] = 0.f; rsq[tid] = 0.f; }

    float acc[4][12];
#pragma unroll
    for (int i = 0; i < 4; ++i)
#pragma unroll
        for (int j = 0; j < 12; ++j) acc[i][j] = 0.f;

    float psum[4] = {0.f, 0.f, 0.f, 0.f};
    float psq[4]  = {0.f, 0.f, 0.f, 0.f};

    for (int s = 0; s < 8; ++s) {
        const int s0 = (s >> 2) & 1, s1 = (s >> 1) & 1, s2 = s & 1;

        __syncthreads();   // prior chunk fully consumed (also covers rsum init on s=0)

        // ---- gather y chunk: 64 rows x 96 contiguous channels, write transposed ----
        for (int i = tid; i < BM * 24; i += TB) {
            int r = i / 24;
            int v = i - r * 24;                       // float4 index within the 96 channels
            int m  = bm * BM + r;
            int ww = m & 31;
            int hh = (m >> 5) & 31;
            int dd = (m >> 10) & 31;
            int bb = m >> 15;
            int off = ((((bb * 64 + 2 * dd + s0) * 64) + (2 * hh + s1)) * 64 + (2 * ww + s2)) * CH + v * 4;
            float4 val = *(const float4*)(x + off);
            int k = v * 4;
            ys[(k + 0) * BMP + r] = val.x;
            ys[(k + 1) * BMP + r] = val.y;
            ys[(k + 2) * BMP + r] = val.z;
            ys[(k + 3) * BMP + r] = val.w;
        }

        // ---- load W chunk (contiguous in WgT) ----
        {
            const float4* wsrc = (const float4*)(g_WgT + s * KC * NDIM);
            float4* wdst = (float4*)ws;
            for (int i = tid; i < KC * NDIM / 4; i += TB) wdst[i] = wsrc[i];
        }

        __syncthreads();

        // ---- GEMM over this chunk ----
        for (int k = 0; k < KC; ++k) {
            float4 yv = *(const float4*)(ys + k * BMP + r0);
            const float4* wrow = (const float4*)(ws + k * NDIM) + tx * 3;
            float4 w0 = wrow[0], w1 = wrow[1], w2 = wrow[2];
            float yr[4] = {yv.x, yv.y, yv.z, yv.w};
            float wc[12] = {w0.x, w0.y, w0.z, w0.w,
                            w1.x, w1.y, w1.z, w1.w,
                            w2.x, w2.y, w2.z, w2.w};
#pragma unroll
            for (int i = 0; i < 4; ++i)
#pragma unroll
                for (int j = 0; j < 12; ++j)
                    acc[i][j] = fmaf(yr[i], wc[j], acc[i][j]);
        }

        // ---- LN stats side-band (partitioned across tx, reduced at the end) ----
        for (int k = tx; k < KC; k += 16) {
            float4 yv = *(const float4*)(ys + k * BMP + r0);
            psum[0] += yv.x; psq[0] = fmaf(yv.x, yv.x, psq[0]);
            psum[1] += yv.y; psq[1] = fmaf(yv.y, yv.y, psq[1]);
            psum[2] += yv.z; psq[2] = fmaf(yv.z, yv.z, psq[2]);
            psum[3] += yv.w; psq[3] = fmaf(yv.w, yv.w, psq[3]);
        }
    }

#pragma unroll
    for (int i = 0; i < 4; ++i) {
        atomicAdd(&rsum[r0 + i], psum[i]);
        atomicAdd(&rsq[r0 + i], psq[i]);
    }
    __syncthreads();

    // ---- epilogue: fold LN + write out ----
    float sv[12], bv[12];
#pragma unroll
    for (int j = 0; j < 12; ++j) {
        sv[j] = g_s[c0 + j];
        bv[j] = g_bias[c0 + j];
    }

#pragma unroll
    for (int i = 0; i < 4; ++i) {
        int r = r0 + i;
        int m = bm * BM + r;
        float mu  = rsum[r] * (1.f / 768.f);
        float var = rsq[r] * (1.f / 768.f) - mu * mu;
        float rs  = rsqrtf(var + 1e-5f);
        float rm  = rs * mu;
        float vals[12];
#pragma unroll
        for (int j = 0; j < 12; ++j)
            vals[j] = fmaf(rs, acc[i][j], bv[j] - rm * sv[j]);
        float* op = out + (size_t)m * NDIM + c0;
        ((float4*)op)[0] = *(float4*)&vals[0];
        ((float4*)op)[1] = *(float4*)&vals[4];
        ((float4*)op)[2] = *(float4*)&vals[8];
    }
}

extern "C" void kernel_launch(void* const* d_in, const int* in_sizes, int n_in,
                              void* d_out, int out_size) {
    const float* x    = (const float*)d_in[0];   // [2,64,64,64,96]
    const float* ln_w = (const float*)d_in[1];   // [768]
    const float* ln_b = (const float*)d_in[2];   // [768]
    const float* W    = (const float*)d_in[3];   // [192,768]
    float* out = (float*)d_out;                  // [65536,192]

    (void)in_sizes; (void)n_in; (void)out_size;

    static_assert(SMEM_FLOATS * 4 < 232000, "smem budget");
    cudaFuncSetAttribute(pm_main, cudaFuncAttributeMaxDynamicSharedMemorySize,
                         SMEM_FLOATS * 4);

    pm_prep_wgt<<<(KDIM * NDIM + 255) / 256, 256>>>(ln_w, W);
    pm_prep_cols<<<1, NDIM>>>(ln_w, ln_b, W);
    pm_main<<<M_TOTAL / BM, TB, SMEM_FLOATS * 4>>>(x, out);
}

// round 4
// speedup vs baseline: 2.3909x; 2.3909x over previous
#include <cuda_runtime.h>
#include <cstdint>

// PatchMerging fused as tf32 mma.sync GEMM (base sm_103 target — no tcgen05 here):
//   out[m,o] = rstd_m * dot(y_m, Wg[o,:]) + (bias_o - rstd_m*mu_m*s_o)
// y = raw gathered x (LN folded into epilogue), Wg[o][c] = ln_w[c]*W[o][c].

#define M_TOTAL 65536
#define KDIM    768
#define NDIM    192
#define CH      96
#define BM      128
#define TB      256
#define NCHUNK  24       // K chunks of 32 floats
#define APITCH  36       // padded A row pitch (floats) in smem

// ---- device scratch (no allocs allowed) ----
// B in mma-fragment-major order, tf32-rounded:
// idx = chunk*6144 + ((nt*4 + ks)*32 + t)*2 + slot
//   k = chunk*32 + ks*8 + slot*4 + (t&3),  n = nt*8 + (t>>2)
__device__ uint32_t g_WgF[NCHUNK * 6144];
__device__ float g_s[NDIM];
__device__ float g_bias[NDIM];

__device__ __forceinline__ uint32_t f2tf32(float f) {
    uint32_t r;
    asm("cvt.rna.tf32.f32 %0, %1;" : "=r"(r) : "f"(f));
    return r;
}

#define MMA_TF32(d, a, b0, b1)                                              \
    asm volatile("mma.sync.aligned.m16n8k8.row.col.f32.tf32.tf32.f32 "      \
                 "{%0,%1,%2,%3}, {%4,%5,%6,%7}, {%8,%9}, {%0,%1,%2,%3};"    \
                 : "+f"((d)[0]), "+f"((d)[1]), "+f"((d)[2]), "+f"((d)[3])   \
                 : "r"((a)[0]), "r"((a)[1]), "r"((a)[2]), "r"((a)[3]),      \
                   "r"(b0), "r"(b1))

__device__ __forceinline__ void cp_async16(uint32_t dst, const void* src) {
    asm volatile("cp.async.cg.shared.global [%0], [%1], 16;" :: "r"(dst), "l"(src));
}

// ---- prep kernels ----
__global__ void pm_prep_wgt(const float* __restrict__ ln_w, const float* __restrict__ W) {
    int idx = blockIdx.x * blockDim.x + threadIdx.x;
    if (idx < NCHUNK * 6144) {
        int chunk = idx / 6144, rem = idx % 6144;
        int slot = rem & 1, pair = rem >> 1;
        int t = pair & 31, tmp = pair >> 5;
        int ks = tmp & 3, nt = tmp >> 2;
        int k = chunk * 32 + ks * 8 + slot * 4 + (t & 3);
        int n = nt * 8 + (t >> 2);
        g_WgF[idx] = f2tf32(ln_w[k] * W[n * KDIM + k]);
    }
}
__global__ void pm_prep_cols(const float* __restrict__ ln_w, const float* __restrict__ ln_b,
                             const float* __restrict__ W) {
    int o = threadIdx.x;
    if (o < NDIM) {
        float s = 0.f, b = 0.f;
        const float* wr = W + o * KDIM;
        for (int c = 0; c < KDIM; ++c) {
            float w = wr[c];
            s = fmaf(ln_w[c], w, s);
            b = fmaf(ln_b[c], w, b);
        }
        g_s[o] = s;
        g_bias[o] = b;
    }
}

// ---- smem float-index layout ----
#define SM_A0    0          // 128*36 = 4608
#define SM_A1    4608
#define SM_B0    9216       // 6144
#define SM_B1    15360
#define SM_PSUM  21504      // 256
#define SM_PSQ   21760      // 256
#define SM_RSTD  22016      // 128
#define SM_RMU   22144      // 128
#define SM_SFOLD 22272      // 192
#define SM_BFOLD 22464      // 192
#define SM_FLOATS 22656     // 90624 bytes

__global__ __launch_bounds__(TB, 1) void pm_main(const float* __restrict__ x,
                                                 float* __restrict__ out) {
    extern __shared__ float sm[];
    float* As[2] = {sm + SM_A0, sm + SM_A1};
    float* Bs[2] = {sm + SM_B0, sm + SM_B1};

    const int tid = threadIdx.x, lane = tid & 31, wid = tid >> 5;
    const int mw = wid >> 1, nw = wid & 1;
    const int bm = blockIdx.x;

    // A-gather geometry: 2 threads per row
    const int r = tid >> 1, h = tid & 1;
    const int m = bm * BM + r;
    const int ww = m & 31, hh = (m >> 5) & 31, dd = (m >> 10) & 31, bb = m >> 15;
    const float* xbase = x + ((((long)bb * 64 + 2 * dd) * 64 + 2 * hh) * 64 + 2 * ww) * CH + h * 16;

    float acc[2][12][4];
#pragma unroll
    for (int i = 0; i < 2; ++i)
#pragma unroll
        for (int j = 0; j < 12; ++j)
#pragma unroll
            for (int u = 0; u < 4; ++u) acc[i][j][u] = 0.f;

    float psum = 0.f, psq = 0.f;
    float4 av[4];

    auto ldg_chunk = [&](int ch) {
        int seg = ch / 3, sub = ch - seg * 3;
        const float* p = xbase + ((seg >> 2) & 1) * 393216 + ((seg >> 1) & 1) * 6144 +
                         (seg & 1) * 96 + sub * 32;
#pragma unroll
        for (int v = 0; v < 4; ++v) av[v] = *(const float4*)(p + v * 4);
    };
    auto sts_chunk = [&](float* Ad) {
        uint32_t* dst = (uint32_t*)(Ad + r * APITCH + h * 16);
#pragma unroll
        for (int v = 0; v < 4; ++v) {
            float4 t4 = av[v];
            psum += t4.x + t4.y + t4.z + t4.w;
            psq = fmaf(t4.x, t4.x, psq);
            psq = fmaf(t4.y, t4.y, psq);
            psq = fmaf(t4.z, t4.z, psq);
            psq = fmaf(t4.w, t4.w, psq);
            uint4 u;
            u.x = f2tf32(t4.x); u.y = f2tf32(t4.y); u.z = f2tf32(t4.z); u.w = f2tf32(t4.w);
            *(uint4*)(dst + v * 4) = u;
        }
    };
    auto cpB = [&](int ch, float* Bd) {
        const uint4* src = (const uint4*)(g_WgF + ch * 6144);
        uint32_t dst = (uint32_t)__cvta_generic_to_shared(Bd);
#pragma unroll
        for (int i = 0; i < 6; ++i) {
            int idx = tid + i * TB;
            cp_async16(dst + idx * 16, src + idx);
        }
    };
    auto compute = [&](const float* Ad, const float* Bd) {
#pragma unroll
        for (int ks = 0; ks < 4; ++ks) {
            uint32_t a[2][4];
#pragma unroll
            for (int tmi = 0; tmi < 2; ++tmi) {
                const float* ap = Ad + (mw * 32 + tmi * 16 + (lane >> 2)) * APITCH +
                                  ks * 8 + (lane & 3);
                a[tmi][0] = __float_as_uint(ap[0]);
                a[tmi][1] = __float_as_uint(ap[8 * APITCH]);
                a[tmi][2] = __float_as_uint(ap[4]);
                a[tmi][3] = __float_as_uint(ap[8 * APITCH + 4]);
            }
#pragma unroll
            for (int nt = 0; nt < 12; ++nt) {
                float2 b = *(const float2*)(Bd + (((nw * 12 + nt) * 4 + ks) * 32 + lane) * 2);
                uint32_t b0 = __float_as_uint(b.x), b1 = __float_as_uint(b.y);
                MMA_TF32(acc[0][nt], a[0], b0, b1);
                MMA_TF32(acc[1][nt], a[1], b0, b1);
            }
        }
    };

    // prologue
    ldg_chunk(0);
    cpB(0, Bs[0]);
    sts_chunk(As[0]);
    asm volatile("cp.async.commit_group;" ::: "memory");
    asm volatile("cp.async.wait_group 0;" ::: "memory");
    __syncthreads();

    int cur = 0;
    for (int c = 0; c < NCHUNK; ++c) {
        const bool more = (c + 1 < NCHUNK);
        if (more) {
            ldg_chunk(c + 1);
            cpB(c + 1, Bs[cur ^ 1]);
            asm volatile("cp.async.commit_group;" ::: "memory");
        }
        compute(As[cur], Bs[cur]);
        if (more) {
            sts_chunk(As[cur ^ 1]);
            asm volatile("cp.async.wait_group 0;" ::: "memory");
        }
        __syncthreads();
        cur ^= 1;
    }

    // ---- LN stats reduce + fold constants ----
    sm[SM_PSUM + tid] = psum;
    sm[SM_PSQ + tid] = psq;
    if (tid < NDIM) {
        sm[SM_SFOLD + tid] = g_s[tid];
        sm[SM_BFOLD + tid] = g_bias[tid];
    }
    __syncthreads();
    if (tid < BM) {
        float su = sm[SM_PSUM + 2 * tid] + sm[SM_PSUM + 2 * tid + 1];
        float sq = sm[SM_PSQ + 2 * tid] + sm[SM_PSQ + 2 * tid + 1];
        float mu = su * (1.f / 768.f);
        float var = sq * (1.f / 768.f) - mu * mu;
        float rs = rsqrtf(var + 1e-5f);
        sm[SM_RSTD + tid] = rs;
        sm[SM_RMU + tid] = rs * mu;
    }
    __syncthreads();

    // ---- epilogue: LN fold + store ----
#pragma unroll
    for (int tmi = 0; tmi < 2; ++tmi) {
        const int rbase = mw * 32 + tmi * 16 + (lane >> 2);
#pragma unroll
        for (int half = 0; half < 2; ++half) {
            const int rr = rbase + half * 8;
            const float rs = sm[SM_RSTD + rr];
            const float rm = sm[SM_RMU + rr];
            float* op = out + (size_t)(bm * BM + rr) * NDIM;
#pragma unroll
            for (int nt = 0; nt < 12; ++nt) {
                const int n0 = nw * 96 + nt * 8 + (lane & 3) * 2;
                float2 v;
                v.x = fmaf(rs, acc[tmi][nt][half * 2 + 0], sm[SM_BFOLD + n0] - rm * sm[SM_SFOLD + n0]);
                v.y = fmaf(rs, acc[tmi][nt][half * 2 + 1], sm[SM_BFOLD + n0 + 1] - rm * sm[SM_SFOLD + n0 + 1]);
                *(float2*)(op + n0) = v;
            }
        }
    }
}

extern "C" void kernel_launch(void* const* d_in, const int* in_sizes, int n_in,
                              void* d_out, int out_size) {
    const float* x    = (const float*)d_in[0];   // [2,64,64,64,96]
    const float* ln_w = (const float*)d_in[1];   // [768]
    const float* ln_b = (const float*)d_in[2];   // [768]
    const float* W    = (const float*)d_in[3];   // [192,768]
    float* out = (float*)d_out;                  // [65536,192]
    (void)in_sizes; (void)n_in; (void)out_size;

    cudaFuncSetAttribute(pm_main, cudaFuncAttributeMaxDynamicSharedMemorySize,
                         SM_FLOATS * 4);

    pm_prep_wgt<<<(NCHUNK * 6144 + 255) / 256, 256>>>(ln_w, W);
    pm_prep_cols<<<1, NDIM>>>(ln_w, ln_b, W);
    pm_main<<<M_TOTAL / BM, TB, SM_FLOATS * 4>>>(x, out);
}